// round 11
// baseline (speedup 1.0000x reference)
#include <cuda_runtime.h>

// CommNet forward: B=8192, N=64, D=128, O=16
//   H1 = tanh(wH1*obs); C1 = (sum_n H1 - H1)/(N-1)
//   H2 = tanh(wH2*H1 + wC2*C1) + obs ; out = H2 @ w_out + b_out
//
// One CTA per batch element, 128 threads.
// Phase: thread = feature d; obs column read ONCE into x[64] registers.
// GEMV: warp = d-quarter; lane = (agent-octet p, o-quad q); per d:
//   2 h-LDS.128 (natural u64 agent pairs) + 1 w-LDS.128 -> 16 FFMA2.
// 4-way d-reduction via quad-swizzled smem partials overlaid on the tile.
// R11: __launch_bounds__(128,4) caps regs at 128 (4 CTAs/SM, 16 warps) and
//      GEMV unroll 4 keeps the pipeline depth inside the cap without spills.

#define N_AG 64
#define DIM  128
#define OUTD 16
#define PITCH 68   // floats; 17 16B-units (odd) -> conflict-free row-strided 128b ops

typedef unsigned long long u64;

__device__ __forceinline__ float tanh_fast(float x) {
    float y; asm("tanh.approx.f32 %0, %1;" : "=f"(y) : "f"(x)); return y;
}
__device__ __forceinline__ u64 pack2(float lo, float hi) {
    u64 r; asm("mov.b64 %0, {%1, %2};" : "=l"(r) : "f"(lo), "f"(hi)); return r;
}
__device__ __forceinline__ void unpack2(u64 v, float& lo, float& hi) {
    asm("mov.b64 {%0, %1}, %2;" : "=f"(lo), "=f"(hi) : "l"(v));
}
__device__ __forceinline__ void ffma2(u64& d, u64 a, u64 b) {
    asm("fma.rn.f32x2 %0, %1, %2, %0;" : "+l"(d) : "l"(a), "l"(b));
}

__global__ __launch_bounds__(128, 4)
void commnet_kernel(const float* __restrict__ obs,
                    const float* __restrict__ wH1,
                    const float* __restrict__ wH2,
                    const float* __restrict__ wC2,
                    const float* __restrict__ wout,
                    const float* __restrict__ bout,
                    float* __restrict__ out)
{
    // sh: h2 tile [128][68] floats (34,816 B); after GEMV reused as
    //     partials part[4 dg][64 n][16 o] floats (16,384 B).
    __shared__ __align__(16) float sh[DIM * PITCH];
    __shared__ __align__(16) float wsm[DIM * OUTD];   // 8 KB
    __shared__ float bsm[OUTD];

    const int tid = threadIdx.x;                      // = feature d for phase
    const int b   = blockIdx.x;

    // ---- stage w_out / b_out ----
    {
        const float4* w4  = (const float4*)wout;
        float4*       ws4 = (float4*)wsm;
        #pragma unroll
        for (int i = 0; i < 4; i++)
            ws4[i * 128 + tid] = w4[i * 128 + tid];
        if (tid < OUTD) bsm[tid] = bout[tid];
    }

    // ---- obs column d=tid into registers: 64 coalesced LDG.32 (read ONCE) ----
    const float* ob = obs + (size_t)b * (N_AG * DIM) + tid;
    float x[N_AG];
    #pragma unroll
    for (int n = 0; n < N_AG; n++)
        x[n] = ob[n * DIM];

    const float a1 = wH1[tid];
    const float a2 = wH2[tid];
    const float c2 = wC2[tid];

    // ---- pass 1: sum of tanh over agents (registers only) ----
    float sum = 0.0f;
    #pragma unroll
    for (int n = 0; n < N_AG; n++)
        sum += tanh_fast(a1 * x[n]);
    const float inv = 1.0f / (float)(N_AG - 1);

    // ---- pass 2: h2 per chunk of 4 agents -> tile row d, STS.128 ----
    {
        float* row = &sh[tid * PITCH];
        #pragma unroll
        for (int m = 0; m < 16; m++) {
            float h2v[4];
            #pragma unroll
            for (int e = 0; e < 4; e++) {
                float xv = x[4 * m + e];
                float h1 = tanh_fast(a1 * xv);
                h2v[e] = tanh_fast(a2 * h1 + c2 * (sum - h1) * inv) + xv;
            }
            *(float4*)&row[4 * m] = make_float4(h2v[0], h2v[1], h2v[2], h2v[3]);
        }
    }
    __syncthreads();

    // ---- GEMV: warp wd = d-quarter; lane = (p agent-octet, q o-quad) ----
    const int wd = tid >> 5;
    const int p  = (tid >> 2) & 7;
    const int q  = tid & 3;

    u64 acc[4][4];                         // [agent-pair ap][o]; pairs natural
    #pragma unroll
    for (int ap = 0; ap < 4; ap++)
        #pragma unroll
        for (int o = 0; o < 4; o++) acc[ap][o] = 0ull;

    #pragma unroll 4
    for (int i = 0; i < 32; i++) {
        const int d = 32 * wd + i;
        const ulonglong2* hp = (const ulonglong2*)&sh[d * PITCH + 8 * p];
        ulonglong2 h01 = hp[0];            // agents (8p,8p+1),(8p+2,8p+3)
        ulonglong2 h23 = hp[1];            // agents (8p+4,8p+5),(8p+6,8p+7)
        float4 wq = *(const float4*)&wsm[d * OUTD + 4 * q];
        u64 w0 = pack2(wq.x, wq.x);
        u64 w1 = pack2(wq.y, wq.y);
        u64 w2 = pack2(wq.z, wq.z);
        u64 w3 = pack2(wq.w, wq.w);

        ffma2(acc[0][0], h01.x, w0); ffma2(acc[0][1], h01.x, w1);
        ffma2(acc[0][2], h01.x, w2); ffma2(acc[0][3], h01.x, w3);
        ffma2(acc[1][0], h01.y, w0); ffma2(acc[1][1], h01.y, w1);
        ffma2(acc[1][2], h01.y, w2); ffma2(acc[1][3], h01.y, w3);
        ffma2(acc[2][0], h23.x, w0); ffma2(acc[2][1], h23.x, w1);
        ffma2(acc[2][2], h23.x, w2); ffma2(acc[2][3], h23.x, w3);
        ffma2(acc[3][0], h23.y, w0); ffma2(acc[3][1], h23.y, w1);
        ffma2(acc[3][2], h23.y, w2); ffma2(acc[3][3], h23.y, w3);
    }
    __syncthreads();                       // all tile reads complete

    // ---- partials: part[wd][n][16], quad-column swizzle c = q ^ (p&3) ----
    {
        float* part = sh;
        const int c4 = 4 * (q ^ (p & 3));
        #pragma unroll
        for (int ap = 0; ap < 4; ap++) {
            float l0, h0, l1, h1, l2, h2, l3, h3;
            unpack2(acc[ap][0], l0, h0);
            unpack2(acc[ap][1], l1, h1);
            unpack2(acc[ap][2], l2, h2);
            unpack2(acc[ap][3], l3, h3);
            const int n0 = 8 * p + 2 * ap;
            *(float4*)&part[wd * 1024 + n0 * 16 + c4]       = make_float4(l0, l1, l2, l3);
            *(float4*)&part[wd * 1024 + (n0 + 1) * 16 + c4] = make_float4(h0, h1, h2, h3);
        }
    }
    __syncthreads();

    // ---- combine + store: thread t -> agent n = t>>1, o-half (t&1)*8 ----
    {
        const float* part = sh;
        const int n   = tid >> 1;
        const int jh  = tid & 1;
        const int pn3 = (n >> 3) & 3;

        #pragma unroll
        for (int jj = 0; jj < 2; jj++) {
            const int j  = 2 * jh + jj;            // output quad index
            const int c4 = 4 * (j ^ pn3);          // physical column
            float4 s0 = *(const float4*)&part[0 * 1024 + n * 16 + c4];
            float4 s1 = *(const float4*)&part[1 * 1024 + n * 16 + c4];
            float4 s2 = *(const float4*)&part[2 * 1024 + n * 16 + c4];
            float4 s3 = *(const float4*)&part[3 * 1024 + n * 16 + c4];
            float4 bq = *(const float4*)&bsm[4 * j];
            float4 r;
            r.x = s0.x + s1.x + s2.x + s3.x + bq.x;
            r.y = s0.y + s1.y + s2.y + s3.y + bq.y;
            r.z = s0.z + s1.z + s2.z + s3.z + bq.z;
            r.w = s0.w + s1.w + s2.w + s3.w + bq.w;
            *(float4*)&out[(size_t)b * (N_AG * OUTD) + n * OUTD + 4 * j] = r;
        }
    }
}

extern "C" void kernel_launch(void* const* d_in, const int* in_sizes, int n_in,
                              void* d_out, int out_size) {
    const float* obs  = (const float*)d_in[0];
    const float* wH1  = (const float*)d_in[1];
    // d_in[2] = w_C1: multiplies C0 = 0 -> unused
    const float* wH2  = (const float*)d_in[3];
    const float* wC2  = (const float*)d_in[4];
    const float* wout = (const float*)d_in[5];
    const float* bout = (const float*)d_in[6];
    float* out = (float*)d_out;

    int B = in_sizes[0] / (N_AG * DIM);   // 8192
    commnet_kernel<<<B, 128>>>(obs, wH1, wH2, wC2, wout, bout, out);
}